// round 4
// baseline (speedup 1.0000x reference)
#include <cuda_runtime.h>
#include <math.h>
#include <stdint.h>

#define N_NODES 100000
#define N_EDGES 1600000
#define N_GRAPHS 64
#define D 128
#define DV4 32  // D/4 float4 per row

// ---------------- device scratch (static, allocation-free) ----------------
__device__ float g_x[N_NODES * D];     // current node features, pre-scaled by norm_src
__device__ float g_agg[N_NODES * D];   // aggregation output
__device__ int   g_indeg[N_NODES];
__device__ int   g_outdeg[N_NODES];
__device__ int   g_cursor[N_NODES];
__device__ float g_ns[N_NODES];        // rsqrt(out_deg)
__device__ float g_nd[N_NODES];        // rsqrt(in_deg)
__device__ float g_c1[N_NODES];        // nd*ns (folded row scale for GEMM input)
__device__ int   g_rowptr[N_NODES + 1];
__device__ int   g_csrsrc[N_EDGES];    // src node ids grouped by dst
__device__ float g_w5f[D];             // W5 @ fc_w
__device__ float g_bf;                 // b5 . fc_w
__device__ float g_p[N_NODES];         // per-node scalar logit contribution
__device__ int   g_psum[128];          // block partial sums for scan (98 used)

// ---------------- CSR build ----------------
__global__ void k_zero() {
    int i = blockIdx.x * blockDim.x + threadIdx.x;
    if (i < N_NODES) { g_indeg[i] = 0; g_outdeg[i] = 0; g_cursor[i] = 0; }
}

__global__ void k_degree(const int* __restrict__ src, const int* __restrict__ dst) {
    int e = blockIdx.x * blockDim.x + threadIdx.x;
    if (e < N_EDGES) {
        atomicAdd(&g_outdeg[src[e]], 1);
        atomicAdd(&g_indeg[dst[e]], 1);
    }
}

__global__ void k_norms() {
    int i = blockIdx.x * blockDim.x + threadIdx.x;
    if (i < N_NODES) {
        float od = (float)max(g_outdeg[i], 1);
        float id = (float)max(g_indeg[i], 1);
        float ns = rsqrtf(od);
        float nd = rsqrtf(id);
        g_ns[i] = ns; g_nd[i] = nd; g_c1[i] = ns * nd;
    }
}

// ---- 3-phase parallel exclusive scan of g_indeg -> g_rowptr ----
// phase 1: per-block (1024 elems) sums
__global__ void k_scan1() {
    __shared__ int wsum[32];
    int t = threadIdx.x;
    int i = blockIdx.x * 1024 + t;
    int v = (i < N_NODES) ? g_indeg[i] : 0;
    int s = v;
#pragma unroll
    for (int o = 16; o; o >>= 1) s += __shfl_down_sync(0xffffffffu, s, o);
    if ((t & 31) == 0) wsum[t >> 5] = s;
    __syncthreads();
    if (t < 32) {
        int x = wsum[t];
#pragma unroll
        for (int o = 16; o; o >>= 1) x += __shfl_down_sync(0xffffffffu, x, o);
        if (t == 0) g_psum[blockIdx.x] = x;
    }
}

// phase 2: exclusive scan of the 98 block sums (1 block, 128 threads)
__global__ void k_scan2() {
    __shared__ int wtot[4];
    int t = threadIdx.x;  // 128
    int lane = t & 31, w = t >> 5;
    int nblk = (N_NODES + 1023) / 1024;  // 98
    int v = (t < nblk) ? g_psum[t] : 0;
    int incl = v;
#pragma unroll
    for (int o = 1; o < 32; o <<= 1) {
        int n = __shfl_up_sync(0xffffffffu, incl, o);
        if (lane >= o) incl += n;
    }
    if (lane == 31) wtot[w] = incl;
    __syncthreads();
    int off = 0;
    for (int k = 0; k < w; k++) off += wtot[k];
    if (t < nblk) g_psum[t] = incl - v + off;  // exclusive prefix
}

// phase 3: per-block exclusive scan + block offset -> g_rowptr
__global__ void k_scan3() {
    __shared__ int wtot[32];
    int t = threadIdx.x;  // 1024
    int lane = t & 31, w = t >> 5;
    int i = blockIdx.x * 1024 + t;
    int v = (i < N_NODES) ? g_indeg[i] : 0;
    int incl = v;
#pragma unroll
    for (int o = 1; o < 32; o <<= 1) {
        int n = __shfl_up_sync(0xffffffffu, incl, o);
        if (lane >= o) incl += n;
    }
    if (lane == 31) wtot[w] = incl;
    __syncthreads();
    if (t < 32) {
        int x = wtot[t];
#pragma unroll
        for (int o = 1; o < 32; o <<= 1) {
            int n = __shfl_up_sync(0xffffffffu, x, o);
            if (lane >= o) x += n;
        }
        wtot[t] = x;  // inclusive over warp sums
    }
    __syncthreads();
    int off = g_psum[blockIdx.x] + (w ? wtot[w - 1] : 0);
    int excl = incl - v + off;
    if (i < N_NODES) {
        g_rowptr[i] = excl;
        if (i == N_NODES - 1) g_rowptr[N_NODES] = excl + v;
    }
}

__global__ void k_fill(const int* __restrict__ src, const int* __restrict__ dst) {
    int e = blockIdx.x * blockDim.x + threadIdx.x;
    if (e < N_EDGES) {
        int d = dst[e];
        int pos = atomicAdd(&g_cursor[d], 1);
        g_csrsrc[g_rowptr[d] + pos] = src[e];
    }
}

// g_x = h * norm_src  (row scale)
__global__ void k_scale0(const float* __restrict__ h) {
    int idx = blockIdx.x * blockDim.x + threadIdx.x;  // float4 index
    if (idx < N_NODES * DV4) {
        int row = idx >> 5;
        float s = g_ns[row];
        float4 v = ((const float4*)h)[idx];
        v.x *= s; v.y *= s; v.z *= s; v.w *= s;
        ((float4*)g_x)[idx] = v;
    }
}

// ---------------- per-layer aggregation: warp per dst node ----------------
__global__ void k_aggregate() {
    int warp = (blockIdx.x * blockDim.x + threadIdx.x) >> 5;
    int lane = threadIdx.x & 31;
    if (warp >= N_NODES) return;
    int e0 = g_rowptr[warp];
    int e1 = g_rowptr[warp + 1];
    const float4* __restrict__ x4 = (const float4*)g_x;
    float4 a0 = make_float4(0.f, 0.f, 0.f, 0.f);
    float4 a1 = make_float4(0.f, 0.f, 0.f, 0.f);
    float4 a2 = make_float4(0.f, 0.f, 0.f, 0.f);
    float4 a3 = make_float4(0.f, 0.f, 0.f, 0.f);
    int j = e0;
    for (; j + 3 < e1; j += 4) {
        int s0 = __ldg(&g_csrsrc[j]);
        int s1 = __ldg(&g_csrsrc[j + 1]);
        int s2 = __ldg(&g_csrsrc[j + 2]);
        int s3 = __ldg(&g_csrsrc[j + 3]);
        float4 v0 = __ldg(&x4[s0 * DV4 + lane]);
        float4 v1 = __ldg(&x4[s1 * DV4 + lane]);
        float4 v2 = __ldg(&x4[s2 * DV4 + lane]);
        float4 v3 = __ldg(&x4[s3 * DV4 + lane]);
        a0.x += v0.x; a0.y += v0.y; a0.z += v0.z; a0.w += v0.w;
        a1.x += v1.x; a1.y += v1.y; a1.z += v1.z; a1.w += v1.w;
        a2.x += v2.x; a2.y += v2.y; a2.z += v2.z; a2.w += v2.w;
        a3.x += v3.x; a3.y += v3.y; a3.z += v3.z; a3.w += v3.w;
    }
    for (; j < e1; j++) {
        int s0 = __ldg(&g_csrsrc[j]);
        float4 v0 = __ldg(&x4[s0 * DV4 + lane]);
        a0.x += v0.x; a0.y += v0.y; a0.z += v0.z; a0.w += v0.w;
    }
    a0.x += a1.x + a2.x + a3.x;
    a0.y += a1.y + a2.y + a3.y;
    a0.z += a1.z + a2.z + a3.z;
    a0.w += a1.w + a2.w + a3.w;
    ((float4*)g_agg)[warp * DV4 + lane] = a0;
}

// ---------------- tensor-core GEMM (split-tf32): g_x = (g_agg*c1)@W + b*ns -----
// Block: 256 thr, tile M=64, N=128, k-chunk 32. smem = 48KB exactly.
// 3xTF32 trick: D = Ahi*Bhi + Alo*Bhi + Ahi*Blo  (error ~2^-22)
__device__ __forceinline__ void split_tf32(float x, uint32_t& hi, uint32_t& lo) {
    uint32_t h;
    asm("cvt.rna.tf32.f32 %0, %1;" : "=r"(h) : "f"(x));
    float l = x - __uint_as_float(h);
    uint32_t lb;
    asm("cvt.rna.tf32.f32 %0, %1;" : "=r"(lb) : "f"(l));
    hi = h; lo = lb;
}

__device__ __forceinline__ void mma_tf32(float* c, const uint32_t* a, uint32_t b0, uint32_t b1) {
    asm volatile(
        "mma.sync.aligned.m16n8k8.row.col.f32.tf32.tf32.f32 "
        "{%0,%1,%2,%3}, {%4,%5,%6,%7}, {%8,%9}, {%0,%1,%2,%3};"
        : "+f"(c[0]), "+f"(c[1]), "+f"(c[2]), "+f"(c[3])
        : "r"(a[0]), "r"(a[1]), "r"(a[2]), "r"(a[3]), "r"(b0), "r"(b1));
}

__global__ void __launch_bounds__(256) k_gemm_tc(const float* __restrict__ W,
                                                const float* __restrict__ b) {
    __shared__ uint32_t sAhi[64 * 32];
    __shared__ uint32_t sAlo[64 * 32];
    __shared__ uint32_t sWhi[32 * 128];
    __shared__ uint32_t sWlo[32 * 128];
    int t = threadIdx.x;
    int row0 = blockIdx.x * 64;
    int wid = t >> 5, lane = t & 31;
    int wr = (wid >> 1) << 4;   // warp row base: 0,16,32,48
    int wc = (wid & 1) << 6;    // warp col base: 0,64
    int qr = lane >> 2, qk = lane & 3;

    float acc[8][4];
#pragma unroll
    for (int nt = 0; nt < 8; nt++)
#pragma unroll
        for (int c = 0; c < 4; c++) acc[nt][c] = 0.f;

    for (int kc = 0; kc < 128; kc += 32) {
        // load W chunk [32][128]: 1024 float4
#pragma unroll
        for (int i = 0; i < 4; i++) {
            int idx = t + i * 256;
            int r = idx >> 5;
            int c4 = idx & 31;
            float4 v = ((const float4*)W)[(kc + r) * 32 + c4];
            int sw = (r & 3) << 3;
            uint32_t hi, lo;
            int cb = c4 * 4;
            split_tf32(v.x, hi, lo); sWhi[r * 128 + ((cb + 0) ^ sw)] = hi; sWlo[r * 128 + ((cb + 0) ^ sw)] = lo;
            split_tf32(v.y, hi, lo); sWhi[r * 128 + ((cb + 1) ^ sw)] = hi; sWlo[r * 128 + ((cb + 1) ^ sw)] = lo;
            split_tf32(v.z, hi, lo); sWhi[r * 128 + ((cb + 2) ^ sw)] = hi; sWlo[r * 128 + ((cb + 2) ^ sw)] = lo;
            split_tf32(v.w, hi, lo); sWhi[r * 128 + ((cb + 3) ^ sw)] = hi; sWlo[r * 128 + ((cb + 3) ^ sw)] = lo;
        }
        // load A chunk [64][32] scaled: 512 float4
#pragma unroll
        for (int i = 0; i < 2; i++) {
            int idx = t + i * 256;
            int r = idx >> 3;
            int c4 = idx & 7;
            int grow = row0 + r;
            float4 v = make_float4(0.f, 0.f, 0.f, 0.f);
            float sc = 0.f;
            if (grow < N_NODES) {
                sc = g_c1[grow];
                v = ((const float4*)g_agg)[grow * 32 + (kc >> 2) + c4];
            }
            v.x *= sc; v.y *= sc; v.z *= sc; v.w *= sc;
            int sw = (r & 7) << 2;
            uint32_t hi, lo;
            int kb = c4 * 4;
            split_tf32(v.x, hi, lo); sAhi[r * 32 + ((kb + 0) ^ sw)] = hi; sAlo[r * 32 + ((kb + 0) ^ sw)] = lo;
            split_tf32(v.y, hi, lo); sAhi[r * 32 + ((kb + 1) ^ sw)] = hi; sAlo[r * 32 + ((kb + 1) ^ sw)] = lo;
            split_tf32(v.z, hi, lo); sAhi[r * 32 + ((kb + 2) ^ sw)] = hi; sAlo[r * 32 + ((kb + 2) ^ sw)] = lo;
            split_tf32(v.w, hi, lo); sAhi[r * 32 + ((kb + 3) ^ sw)] = hi; sAlo[r * 32 + ((kb + 3) ^ sw)] = lo;
        }
        __syncthreads();
#pragma unroll
        for (int k8 = 0; k8 < 32; k8 += 8) {
            int r0 = wr + qr, r1 = r0 + 8;
            int asw = qr << 2;
            uint32_t ah[4], al[4];
            ah[0] = sAhi[r0 * 32 + ((k8 + qk) ^ asw)];
            ah[1] = sAhi[r1 * 32 + ((k8 + qk) ^ asw)];
            ah[2] = sAhi[r0 * 32 + ((k8 + qk + 4) ^ asw)];
            ah[3] = sAhi[r1 * 32 + ((k8 + qk + 4) ^ asw)];
            al[0] = sAlo[r0 * 32 + ((k8 + qk) ^ asw)];
            al[1] = sAlo[r1 * 32 + ((k8 + qk) ^ asw)];
            al[2] = sAlo[r0 * 32 + ((k8 + qk + 4) ^ asw)];
            al[3] = sAlo[r1 * 32 + ((k8 + qk + 4) ^ asw)];
            int rk0 = k8 + qk, rk1 = rk0 + 4;
            int wsw = qk << 3;  // (rk0&3)==(rk1&3)==qk
#pragma unroll
            for (int nt = 0; nt < 8; nt++) {
                int coln = wc + nt * 8 + qr;
                uint32_t bh0 = sWhi[rk0 * 128 + (coln ^ wsw)];
                uint32_t bh1 = sWhi[rk1 * 128 + (coln ^ wsw)];
                uint32_t bl0 = sWlo[rk0 * 128 + (coln ^ wsw)];
                uint32_t bl1 = sWlo[rk1 * 128 + (coln ^ wsw)];
                mma_tf32(acc[nt], ah, bh0, bh1);
                mma_tf32(acc[nt], al, bh0, bh1);
                mma_tf32(acc[nt], ah, bl0, bl1);
            }
        }
        __syncthreads();
    }

    // store with bias*ns folding; c0,c1 are adjacent cols -> float2 stores
    int r0g = row0 + wr + qr;
    int r1g = r0g + 8;
    float ns0 = (r0g < N_NODES) ? g_ns[r0g] : 0.f;
    float ns1 = (r1g < N_NODES) ? g_ns[r1g] : 0.f;
#pragma unroll
    for (int nt = 0; nt < 8; nt++) {
        int c0 = wc + nt * 8 + 2 * qk;
        float2 bb = *(const float2*)&b[c0];
        if (r0g < N_NODES) {
            float2 o;
            o.x = acc[nt][0] + bb.x * ns0;
            o.y = acc[nt][1] + bb.y * ns0;
            *(float2*)&g_x[r0g * 128 + c0] = o;
        }
        if (r1g < N_NODES) {
            float2 o;
            o.x = acc[nt][2] + bb.x * ns1;
            o.y = acc[nt][3] + bb.y * ns1;
            *(float2*)&g_x[r1g * 128 + c0] = o;
        }
    }
}

// ---------------- collapsed layer 5 ----------------
__global__ void k_w5f(const float* __restrict__ W5, const float* __restrict__ b5,
                      const float* __restrict__ fcw) {
    int j = threadIdx.x;  // 128
    float s = 0.f;
    for (int o = 0; o < D; o++) s += W5[j * D + o] * fcw[o];
    g_w5f[j] = s;
    if (j == 0) {
        float bb = 0.f;
        for (int o = 0; o < D; o++) bb += b5[o] * fcw[o];
        g_bf = bb;
    }
}

__global__ void k_p() {
    int warp = (blockIdx.x * blockDim.x + threadIdx.x) >> 5;
    int lane = threadIdx.x & 31;
    if (warp >= N_NODES) return;
    float4 v = ((const float4*)g_agg)[warp * DV4 + lane];
    float4 w = ((const float4*)g_w5f)[lane];
    float s = v.x * w.x + v.y * w.y + v.z * w.z + v.w * w.w;
#pragma unroll
    for (int o = 16; o; o >>= 1) s += __shfl_xor_sync(0xffffffffu, s, o);
    if (lane == 0) g_p[warp] = g_nd[warp] * s + g_bf;
}

// single block: segmented reduce (graph_ids are sorted) + sigmoid
__global__ void k_pool(const int* __restrict__ gids, const float* __restrict__ fcb,
                       float* __restrict__ out) {
    __shared__ float gsum[N_GRAPHS];
    __shared__ int gcnt[N_GRAPHS];
    int t = threadIdx.x;  // 1024
    if (t < N_GRAPHS) { gsum[t] = 0.f; gcnt[t] = 0; }
    __syncthreads();
    const int CH = (N_NODES + 1023) / 1024;
    int start = t * CH;
    int end = min(start + CH, N_NODES);
    if (start < end) {
        int curg = gids[start];
        float s = 0.f; int c = 0;
        for (int i = start; i < end; i++) {
            int g = gids[i];
            if (g != curg) {
                atomicAdd(&gsum[curg], s);
                atomicAdd(&gcnt[curg], c);
                curg = g; s = 0.f; c = 0;
            }
            s += g_p[i]; c++;
        }
        atomicAdd(&gsum[curg], s);
        atomicAdd(&gcnt[curg], c);
    }
    __syncthreads();
    if (t < N_GRAPHS) {
        float cnt = fmaxf((float)gcnt[t], 1.0f);
        float v = gsum[t] / cnt + fcb[0];
        out[t] = 1.0f / (1.0f + expf(-v));
    }
}

// ---------------- launch ----------------
extern "C" void kernel_launch(void* const* d_in, const int* in_sizes, int n_in,
                              void* d_out, int out_size) {
    const float* h   = (const float*)d_in[0];
    const int* src   = (const int*)d_in[1];
    const int* dst   = (const int*)d_in[2];
    const int* gids  = (const int*)d_in[3];
    const float* W1  = (const float*)d_in[4];
    const float* b1  = (const float*)d_in[5];
    const float* W2  = (const float*)d_in[6];
    const float* b2  = (const float*)d_in[7];
    const float* W3  = (const float*)d_in[8];
    const float* b3  = (const float*)d_in[9];
    const float* W4  = (const float*)d_in[10];
    const float* b4  = (const float*)d_in[11];
    const float* W5  = (const float*)d_in[12];
    const float* b5  = (const float*)d_in[13];
    const float* fcw = (const float*)d_in[14];
    const float* fcb = (const float*)d_in[15];
    float* out = (float*)d_out;

    const int TB = 256;
    const int scanBlocks = (N_NODES + 1023) / 1024;  // 98
    k_zero<<<(N_NODES + TB - 1) / TB, TB>>>();
    k_degree<<<(N_EDGES + TB - 1) / TB, TB>>>(src, dst);
    k_norms<<<(N_NODES + TB - 1) / TB, TB>>>();
    k_scan1<<<scanBlocks, 1024>>>();
    k_scan2<<<1, 128>>>();
    k_scan3<<<scanBlocks, 1024>>>();
    k_fill<<<(N_EDGES + TB - 1) / TB, TB>>>(src, dst);
    k_scale0<<<(N_NODES * DV4 + TB - 1) / TB, TB>>>(h);
    k_w5f<<<1, 128>>>(W5, b5, fcw);

    const float* Ws[4] = {W1, W2, W3, W4};
    const float* bs[4] = {b1, b2, b3, b4};
    int aggGrid = (N_NODES * 32 + TB - 1) / TB;   // warp per node
    int gemmGrid = (N_NODES + 63) / 64;
    for (int l = 0; l < 4; l++) {
        k_aggregate<<<aggGrid, TB>>>();
        k_gemm_tc<<<gemmGrid, TB>>>(Ws[l], bs[l]);
    }
    k_aggregate<<<aggGrid, TB>>>();
    k_p<<<aggGrid, TB>>>();
    k_pool<<<1, 1024>>>(gids, fcb, out);
}

// round 6
// speedup vs baseline: 5.3731x; 5.3731x over previous
#include <cuda_runtime.h>
#include <math.h>
#include <stdint.h>

#define N_NODES 100000
#define N_EDGES 1600000
#define N_GRAPHS 64
#define D 128

// ---------------- device scratch (static, allocation-free) ----------------
__device__ int   g_indeg[N_NODES];
__device__ int   g_outdeg[N_NODES];
__device__ int   g_cursor[N_NODES];
__device__ float g_ns[N_NODES];        // rsqrt(out_deg)
__device__ float g_nd[N_NODES];        // rsqrt(in_deg)
__device__ float g_c1[N_NODES];        // nd*ns
__device__ int   g_rowptr[N_NODES + 1];
__device__ int   g_csrsrc[N_EDGES];    // src ids grouped by dst
__device__ int   g_psum[128];          // scan partials (98 used)
__device__ float g_d0[D];              // W1 W2 W3 W4 W5 fc_w
__device__ float g_beta[6];            // beta_1..beta_5
__device__ float g_y[N_NODES];         // scalar state (pre-scaled by ns)
__device__ float g_y2[N_NODES];
__device__ float g_p[N_NODES];         // final per-node logit contribution

// ---------------- CSR build ----------------
__global__ void k_zero() {
    int i = blockIdx.x * blockDim.x + threadIdx.x;
    if (i < N_NODES) { g_indeg[i] = 0; g_outdeg[i] = 0; g_cursor[i] = 0; }
}

__global__ void k_degree(const int* __restrict__ src, const int* __restrict__ dst) {
    int e = blockIdx.x * blockDim.x + threadIdx.x;
    if (e < N_EDGES) {
        atomicAdd(&g_outdeg[src[e]], 1);
        atomicAdd(&g_indeg[dst[e]], 1);
    }
}

__global__ void k_norms() {
    int i = blockIdx.x * blockDim.x + threadIdx.x;
    if (i < N_NODES) {
        float od = (float)max(g_outdeg[i], 1);
        float id = (float)max(g_indeg[i], 1);
        float ns = rsqrtf(od);
        float nd = rsqrtf(id);
        g_ns[i] = ns; g_nd[i] = nd; g_c1[i] = ns * nd;
    }
}

// ---- 3-phase parallel exclusive scan of g_indeg -> g_rowptr ----
__global__ void k_scan1() {
    __shared__ int wsum[32];
    int t = threadIdx.x;
    int i = blockIdx.x * 1024 + t;
    int v = (i < N_NODES) ? g_indeg[i] : 0;
    int s = v;
#pragma unroll
    for (int o = 16; o; o >>= 1) s += __shfl_down_sync(0xffffffffu, s, o);
    if ((t & 31) == 0) wsum[t >> 5] = s;
    __syncthreads();
    if (t < 32) {
        int x = wsum[t];
#pragma unroll
        for (int o = 16; o; o >>= 1) x += __shfl_down_sync(0xffffffffu, x, o);
        if (t == 0) g_psum[blockIdx.x] = x;
    }
}

__global__ void k_scan2() {
    __shared__ int wtot[4];
    int t = threadIdx.x;  // 128
    int lane = t & 31, w = t >> 5;
    int nblk = (N_NODES + 1023) / 1024;  // 98
    int v = (t < nblk) ? g_psum[t] : 0;
    int incl = v;
#pragma unroll
    for (int o = 1; o < 32; o <<= 1) {
        int n = __shfl_up_sync(0xffffffffu, incl, o);
        if (lane >= o) incl += n;
    }
    if (lane == 31) wtot[w] = incl;
    __syncthreads();
    int off = 0;
    for (int k = 0; k < w; k++) off += wtot[k];
    if (t < nblk) g_psum[t] = incl - v + off;
}

__global__ void k_scan3() {
    __shared__ int wtot[32];
    int t = threadIdx.x;  // 1024
    int lane = t & 31, w = t >> 5;
    int i = blockIdx.x * 1024 + t;
    int v = (i < N_NODES) ? g_indeg[i] : 0;
    int incl = v;
#pragma unroll
    for (int o = 1; o < 32; o <<= 1) {
        int n = __shfl_up_sync(0xffffffffu, incl, o);
        if (lane >= o) incl += n;
    }
    if (lane == 31) wtot[w] = incl;
    __syncthreads();
    if (t < 32) {
        int x = wtot[t];
#pragma unroll
        for (int o = 1; o < 32; o <<= 1) {
            int n = __shfl_up_sync(0xffffffffu, x, o);
            if (lane >= o) x += n;
        }
        wtot[t] = x;
    }
    __syncthreads();
    int off = g_psum[blockIdx.x] + (w ? wtot[w - 1] : 0);
    int excl = incl - v + off;
    if (i < N_NODES) {
        g_rowptr[i] = excl;
        if (i == N_NODES - 1) g_rowptr[N_NODES] = excl + v;
    }
}

__global__ void k_fill(const int* __restrict__ src, const int* __restrict__ dst) {
    int e = blockIdx.x * blockDim.x + threadIdx.x;
    if (e < N_EDGES) {
        int d = dst[e];
        int pos = atomicAdd(&g_cursor[d], 1);
        g_csrsrc[g_rowptr[d] + pos] = src[e];
    }
}

// ---------------- weight chain: d0 = W1 W2 W3 W4 W5 fcw, beta_k = b_k . d_k ----
__global__ void k_chain(const float* __restrict__ W1, const float* __restrict__ W2,
                        const float* __restrict__ W3, const float* __restrict__ W4,
                        const float* __restrict__ W5,
                        const float* __restrict__ b1, const float* __restrict__ b2,
                        const float* __restrict__ b3, const float* __restrict__ b4,
                        const float* __restrict__ b5, const float* __restrict__ fcw) {
    __shared__ float c[D];
    __shared__ float red[4];
    int t = threadIdx.x;  // 128
    int lane = t & 31, w = t >> 5;
    c[t] = fcw[t];
    __syncthreads();
    const float* Ws[5] = {W5, W4, W3, W2, W1};
    const float* bs[5] = {b5, b4, b3, b2, b1};
    const int bi[5] = {5, 4, 3, 2, 1};
    for (int s = 0; s < 5; s++) {
        // beta = bs[s] . c
        float v = bs[s][t] * c[t];
#pragma unroll
        for (int o = 16; o; o >>= 1) v += __shfl_xor_sync(0xffffffffu, v, o);
        if (lane == 0) red[w] = v;
        __syncthreads();
        if (t == 0) g_beta[bi[s]] = red[0] + red[1] + red[2] + red[3];
        // c = Ws[s] @ c   (row t dot c; W row-major [in][out])
        float acc = 0.f;
        const float4* wr = (const float4*)(Ws[s] + t * D);
#pragma unroll
        for (int j = 0; j < 32; j++) {
            float4 ww = __ldg(&wr[j]);
            acc += ww.x * c[j * 4] + ww.y * c[j * 4 + 1] + ww.z * c[j * 4 + 2] + ww.w * c[j * 4 + 3];
        }
        __syncthreads();
        c[t] = acc;
        __syncthreads();
    }
    g_d0[t] = c[t];
}

// ---------------- q0 = h @ d0, pre-scaled by ns: warp per node ----------------
__global__ void k_q0(const float* __restrict__ h) {
    int warp = (blockIdx.x * blockDim.x + threadIdx.x) >> 5;
    int lane = threadIdx.x & 31;
    if (warp >= N_NODES) return;
    float4 v = __ldg(&((const float4*)h)[warp * 32 + lane]);
    float4 d = ((const float4*)g_d0)[lane];
    float s = v.x * d.x + v.y * d.y + v.z * d.z + v.w * d.w;
#pragma unroll
    for (int o = 16; o; o >>= 1) s += __shfl_xor_sync(0xffffffffu, s, o);
    if (lane == 0) g_y[warp] = g_ns[warp] * s;
}

// ---------------- scalar S-apply: thread per node ----------------
// mode 0: g_y  -> g_y2 (scaled for next layer)
// mode 1: g_y2 -> g_y  (scaled for next layer)
// mode 2: g_y  -> g_p  (final: nd scale, no ns)
__global__ void k_sapply(int k, int mode) {
    int i = blockIdx.x * blockDim.x + threadIdx.x;
    if (i >= N_NODES) return;
    const float* __restrict__ yin = (mode == 1) ? g_y2 : g_y;
    int e0 = g_rowptr[i];
    int e1 = g_rowptr[i + 1];
    float s0 = 0.f, s1 = 0.f, s2 = 0.f, s3 = 0.f;
    int j = e0;
    for (; j + 3 < e1; j += 4) {
        int a0 = __ldg(&g_csrsrc[j]);
        int a1 = __ldg(&g_csrsrc[j + 1]);
        int a2 = __ldg(&g_csrsrc[j + 2]);
        int a3 = __ldg(&g_csrsrc[j + 3]);
        s0 += __ldg(&yin[a0]);
        s1 += __ldg(&yin[a1]);
        s2 += __ldg(&yin[a2]);
        s3 += __ldg(&yin[a3]);
    }
    for (; j < e1; j++) s0 += __ldg(&yin[__ldg(&g_csrsrc[j])]);
    float s = (s0 + s1) + (s2 + s3);
    float beta = g_beta[k];
    if (mode == 2) {
        g_p[i] = g_nd[i] * s + beta;
    } else {
        float o = g_c1[i] * s + g_ns[i] * beta;
        if (mode == 1) g_y[i] = o; else g_y2[i] = o;
    }
}

// ---------------- pool: segmented mean (graph_ids sorted) + sigmoid ----------
__global__ void k_pool(const int* __restrict__ gids, const float* __restrict__ fcb,
                       float* __restrict__ out) {
    __shared__ float gsum[N_GRAPHS];
    __shared__ int gcnt[N_GRAPHS];
    int t = threadIdx.x;  // 1024
    if (t < N_GRAPHS) { gsum[t] = 0.f; gcnt[t] = 0; }
    __syncthreads();
    const int CH = (N_NODES + 1023) / 1024;
    int start = t * CH;
    int end = min(start + CH, N_NODES);
    if (start < end) {
        int curg = gids[start];
        float s = 0.f; int c = 0;
        for (int i = start; i < end; i++) {
            int g = gids[i];
            if (g != curg) {
                atomicAdd(&gsum[curg], s);
                atomicAdd(&gcnt[curg], c);
                curg = g; s = 0.f; c = 0;
            }
            s += g_p[i]; c++;
        }
        atomicAdd(&gsum[curg], s);
        atomicAdd(&gcnt[curg], c);
    }
    __syncthreads();
    if (t < N_GRAPHS) {
        float cnt = fmaxf((float)gcnt[t], 1.0f);
        float v = gsum[t] / cnt + fcb[0];
        out[t] = 1.0f / (1.0f + expf(-v));
    }
}

// ---------------- launch ----------------
extern "C" void kernel_launch(void* const* d_in, const int* in_sizes, int n_in,
                              void* d_out, int out_size) {
    const float* h   = (const float*)d_in[0];
    const int* src   = (const int*)d_in[1];
    const int* dst   = (const int*)d_in[2];
    const int* gids  = (const int*)d_in[3];
    const float* W1  = (const float*)d_in[4];
    const float* b1  = (const float*)d_in[5];
    const float* W2  = (const float*)d_in[6];
    const float* b2  = (const float*)d_in[7];
    const float* W3  = (const float*)d_in[8];
    const float* b3  = (const float*)d_in[9];
    const float* W4  = (const float*)d_in[10];
    const float* b4  = (const float*)d_in[11];
    const float* W5  = (const float*)d_in[12];
    const float* b5  = (const float*)d_in[13];
    const float* fcw = (const float*)d_in[14];
    const float* fcb = (const float*)d_in[15];
    float* out = (float*)d_out;

    const int TB = 256;
    const int scanBlocks = (N_NODES + 1023) / 1024;  // 98
    k_zero<<<(N_NODES + TB - 1) / TB, TB>>>();
    k_degree<<<(N_EDGES + TB - 1) / TB, TB>>>(src, dst);
    k_norms<<<(N_NODES + TB - 1) / TB, TB>>>();
    k_scan1<<<scanBlocks, 1024>>>();
    k_scan2<<<1, 128>>>();
    k_scan3<<<scanBlocks, 1024>>>();
    k_fill<<<(N_EDGES + TB - 1) / TB, TB>>>(src, dst);
    k_chain<<<1, 128>>>(W1, W2, W3, W4, W5, b1, b2, b3, b4, b5, fcw);
    k_q0<<<(N_NODES * 32 + TB - 1) / TB, TB>>>(h);

    int nodeGrid = (N_NODES + TB - 1) / TB;
    k_sapply<<<nodeGrid, TB>>>(1, 0);  // g_y  -> g_y2
    k_sapply<<<nodeGrid, TB>>>(2, 1);  // g_y2 -> g_y
    k_sapply<<<nodeGrid, TB>>>(3, 0);  // g_y  -> g_y2
    k_sapply<<<nodeGrid, TB>>>(4, 1);  // g_y2 -> g_y
    k_sapply<<<nodeGrid, TB>>>(5, 2);  // g_y  -> g_p
    k_pool<<<1, 1024>>>(gids, fcb, out);
}